// round 7
// baseline (speedup 1.0000x reference)
#include <cuda_runtime.h>
#include <cuda_bf16.h>
#include <math.h>

#define NN 50000
#define NE 800000
#define NT (NE + NN)
#define FIN 128
#define F1 256
#define H1HEADS 4
#define F2 64
#define NEG_SLOPE 0.2f

// -------- scratch (device globals) --------
__device__ float g_h1[NN * F1];
__device__ float g_out1[NN * F1];
__device__ float g_h2[NN * F2];
__device__ float g_as1[NN * H1HEADS];
__device__ float g_ad1[NN * H1HEADS];
__device__ float g_as2[NN];
__device__ float g_ad2[NN];
__device__ float g_p1[(long long)NT * 4];   // per-(edge,head) softmax numerators
__device__ float g_den1[NN * 4];
__device__ float g_p2[NT];
__device__ float g_den2[NN];
__device__ int   g_deg[NN];
__device__ int   g_rowptr[NN + 1];
__device__ int   g_fill[NN];
__device__ int   g_csrsrc[NT];

// ---------------- packed fp32x2 helpers (sm_100+) ----------------
__device__ __forceinline__ unsigned long long pack2(float x) {
    unsigned long long r;
    asm("mov.b64 %0, {%1, %1};" : "=l"(r) : "f"(x));
    return r;
}
__device__ __forceinline__ void fma2(unsigned long long& d,
                                     unsigned long long a,
                                     unsigned long long b) {
    asm("fma.rn.f32x2 %0, %1, %2, %0;" : "+l"(d) : "l"(a), "l"(b));
}

__device__ __forceinline__ float lrelu(float x) {
    return x > 0.f ? x : NEG_SLOPE * x;
}

// ---------------- CSR build ----------------
__global__ void k_deg_init() {
    int i = blockIdx.x * blockDim.x + threadIdx.x;
    if (i < NN) g_deg[i] = 1;   // self loop
}

__global__ void k_count(const int* __restrict__ edge) {
    int e = blockIdx.x * blockDim.x + threadIdx.x;
    if (e < NE) atomicAdd(&g_deg[edge[NE + e]], 1);
}

__global__ __launch_bounds__(1024) void k_scan() {
    __shared__ int sw[33];
    __shared__ int s_base;
    if (threadIdx.x == 0) s_base = 0;
    __syncthreads();
    const int lane = threadIdx.x & 31, warp = threadIdx.x >> 5;
    for (int base = 0; base < NN; base += 4096) {
        int idx = base + threadIdx.x * 4;
        int v0 = 0, v1 = 0, v2 = 0, v3 = 0;
        if (idx + 3 < NN) {
            int4 v = *(const int4*)&g_deg[idx];
            v0 = v.x; v1 = v.y; v2 = v.z; v3 = v.w;
        } else {
            if (idx     < NN) v0 = g_deg[idx];
            if (idx + 1 < NN) v1 = g_deg[idx + 1];
            if (idx + 2 < NN) v2 = g_deg[idx + 2];
            if (idx + 3 < NN) v3 = g_deg[idx + 3];
        }
        int s0 = v0, s1 = s0 + v1, s2 = s1 + v2, s3 = s2 + v3;
        int incl = s3;
        #pragma unroll
        for (int o = 1; o < 32; o <<= 1) {
            int t = __shfl_up_sync(0xffffffffu, incl, o);
            if (lane >= o) incl += t;
        }
        if (lane == 31) sw[warp + 1] = incl;
        __syncthreads();
        if (threadIdx.x == 0) {
            sw[0] = 0;
            int acc = 0;
            #pragma unroll
            for (int w = 1; w <= 32; w++) { acc += sw[w]; sw[w] = acc; }
        }
        __syncthreads();
        int tbase = s_base + sw[warp] + (incl - s3);
        if (idx     < NN) { g_rowptr[idx]     = tbase;      g_fill[idx]     = tbase; }
        if (idx + 1 < NN) { g_rowptr[idx + 1] = tbase + s0; g_fill[idx + 1] = tbase + s0; }
        if (idx + 2 < NN) { g_rowptr[idx + 2] = tbase + s1; g_fill[idx + 2] = tbase + s1; }
        if (idx + 3 < NN) { g_rowptr[idx + 3] = tbase + s2; g_fill[idx + 3] = tbase + s2; }
        __syncthreads();
        if (threadIdx.x == 0) s_base += sw[32];
        __syncthreads();
    }
    if (threadIdx.x == 0) g_rowptr[NN] = s_base;
}

__global__ void k_scatter(const int* __restrict__ edge) {
    int t = blockIdx.x * blockDim.x + threadIdx.x;
    if (t < NE) {
        int d = edge[NE + t];
        int s = edge[t];
        int pos = atomicAdd(&g_fill[d], 1);
        g_csrsrc[pos] = s;
    } else if (t < NT) {
        int i = t - NE;
        int pos = atomicAdd(&g_fill[i], 1);
        g_csrsrc[pos] = i;
    }
}

// --- double-buffered SGEMM, packed f32x2 mainloop (pairs along N) ---
template <int BM, int BN, int BK, int TM, int TN>
__device__ __forceinline__
void sgemm_body(const float* __restrict__ A, const float* __restrict__ B,
                float* __restrict__ C, int M, int K, int N) {
    constexpr int THREADS = 256;
    constexpr int NA = BM * BK / 4 / THREADS;
    constexpr int NB = BK * BN / 4 / THREADS;
    constexpr int TN2 = TN / 2;
    __shared__ float As[2][BK][BM + 4];
    __shared__ float Bs[2][BK][BN];
    const int tx = threadIdx.x;
    const int tcol = tx % (BN / TN);
    const int trow = tx / (BN / TN);
    const int rowBase = blockIdx.x * BM;
    const int colBase = blockIdx.y * BN;

    float4 aReg[NA], bReg[NB];

    unsigned long long acc2[TM][TN2];
    #pragma unroll
    for (int i = 0; i < TM; i++)
        #pragma unroll
        for (int j = 0; j < TN2; j++) acc2[i][j] = 0ull;

    #pragma unroll
    for (int i = 0; i < NA; i++) {
        int id = tx + i * THREADS;
        int r = id / (BK / 4), c4 = id % (BK / 4);
        int gr = rowBase + r;
        aReg[i] = (gr < M) ? *(const float4*)&A[(long long)gr * K + c4 * 4]
                           : make_float4(0.f, 0.f, 0.f, 0.f);
    }
    #pragma unroll
    for (int i = 0; i < NB; i++) {
        int id = tx + i * THREADS;
        int r = id / (BN / 4), c4 = id % (BN / 4);
        bReg[i] = *(const float4*)&B[r * N + colBase + c4 * 4];
    }
    #pragma unroll
    for (int i = 0; i < NA; i++) {
        int id = tx + i * THREADS;
        int r = id / (BK / 4), c4 = id % (BK / 4);
        As[0][c4 * 4 + 0][r] = aReg[i].x;
        As[0][c4 * 4 + 1][r] = aReg[i].y;
        As[0][c4 * 4 + 2][r] = aReg[i].z;
        As[0][c4 * 4 + 3][r] = aReg[i].w;
    }
    #pragma unroll
    for (int i = 0; i < NB; i++) {
        int id = tx + i * THREADS;
        int r = id / (BN / 4), c4 = id % (BN / 4);
        *(float4*)&Bs[0][r][c4 * 4] = bReg[i];
    }
    __syncthreads();

    const int nt = K / BK;
    for (int t = 0; t < nt; t++) {
        const int buf = t & 1;
        if (t + 1 < nt) {
            const int k0 = (t + 1) * BK;
            #pragma unroll
            for (int i = 0; i < NA; i++) {
                int id = tx + i * THREADS;
                int r = id / (BK / 4), c4 = id % (BK / 4);
                int gr = rowBase + r;
                aReg[i] = (gr < M) ? *(const float4*)&A[(long long)gr * K + k0 + c4 * 4]
                                   : make_float4(0.f, 0.f, 0.f, 0.f);
            }
            #pragma unroll
            for (int i = 0; i < NB; i++) {
                int id = tx + i * THREADS;
                int r = id / (BN / 4), c4 = id % (BN / 4);
                bReg[i] = *(const float4*)&B[(k0 + r) * N + colBase + c4 * 4];
            }
        }
        #pragma unroll
        for (int k = 0; k < BK; k++) {
            float a[TM];
            unsigned long long a2[TM], b2[TN2];
            #pragma unroll
            for (int i = 0; i < TM; i += 4)
                *(float4*)&a[i] = *(const float4*)&As[buf][k][trow * TM + i];
            #pragma unroll
            for (int i = 0; i < TM; i++) a2[i] = pack2(a[i]);
            #pragma unroll
            for (int j = 0; j < TN2; j += 2) {
                ulonglong2 bb = *(const ulonglong2*)&Bs[buf][k][tcol * TN + j * 2];
                b2[j] = bb.x; b2[j + 1] = bb.y;
            }
            #pragma unroll
            for (int i = 0; i < TM; i++)
                #pragma unroll
                for (int j = 0; j < TN2; j++)
                    fma2(acc2[i][j], a2[i], b2[j]);
        }
        if (t + 1 < nt) {
            __syncthreads();
            #pragma unroll
            for (int i = 0; i < NA; i++) {
                int id = tx + i * THREADS;
                int r = id / (BK / 4), c4 = id % (BK / 4);
                As[buf ^ 1][c4 * 4 + 0][r] = aReg[i].x;
                As[buf ^ 1][c4 * 4 + 1][r] = aReg[i].y;
                As[buf ^ 1][c4 * 4 + 2][r] = aReg[i].z;
                As[buf ^ 1][c4 * 4 + 3][r] = aReg[i].w;
            }
            #pragma unroll
            for (int i = 0; i < NB; i++) {
                int id = tx + i * THREADS;
                int r = id / (BN / 4), c4 = id % (BN / 4);
                *(float4*)&Bs[buf ^ 1][r][c4 * 4] = bReg[i];
            }
            __syncthreads();
        }
    }
    #pragma unroll
    for (int i = 0; i < TM; i++) {
        int gr = rowBase + trow * TM + i;
        if (gr < M) {
            #pragma unroll
            for (int j = 0; j < TN2; j += 2) {
                ulonglong2 st;
                st.x = acc2[i][j];
                st.y = acc2[i][j + 1];
                *(ulonglong2*)&C[(long long)gr * N + colBase + tcol * TN + j * 2] = st;
            }
        }
    }
}

__global__ __launch_bounds__(256, 2)
void sgemm1_kernel(const float* __restrict__ A, const float* __restrict__ B) {
    sgemm_body<128, 128, 16, 8, 8>(A, B, g_h1, NN, FIN, F1);
}

__global__ __launch_bounds__(256, 2)
void sgemm2_kernel(const float* __restrict__ B) {
    sgemm_body<128, 64, 16, 8, 4>(g_out1, B, g_h2, NN, F1, F2);
}

// ---------------- alpha projections ----------------
__global__ void alpha1_kernel(const float* __restrict__ a_src,
                              const float* __restrict__ a_dst) {
    int warp = threadIdx.x >> 5, lane = threadIdx.x & 31;
    int node = blockIdx.x * 2 + (warp >> 2);
    int h = warp & 3;
    if (node >= NN) return;
    const float* row = g_h1 + (long long)node * F1 + h * 64;
    float v0 = row[lane], v1 = row[lane + 32];
    float s = v0 * a_src[h * 64 + lane] + v1 * a_src[h * 64 + lane + 32];
    float d = v0 * a_dst[h * 64 + lane] + v1 * a_dst[h * 64 + lane + 32];
    #pragma unroll
    for (int o = 16; o > 0; o >>= 1) {
        s += __shfl_down_sync(0xffffffffu, s, o);
        d += __shfl_down_sync(0xffffffffu, d, o);
    }
    if (lane == 0) { g_as1[node * 4 + h] = s; g_ad1[node * 4 + h] = d; }
}

__global__ void alpha2_kernel(const float* __restrict__ a_src,
                              const float* __restrict__ a_dst) {
    int warp = threadIdx.x >> 5, lane = threadIdx.x & 31;
    int node = blockIdx.x * 8 + warp;
    if (node >= NN) return;
    float v0 = g_h2[(long long)node * F2 + lane];
    float v1 = g_h2[(long long)node * F2 + lane + 32];
    float s = v0 * a_src[lane] + v1 * a_src[lane + 32];
    float d = v0 * a_dst[lane] + v1 * a_dst[lane + 32];
    #pragma unroll
    for (int o = 16; o > 0; o >>= 1) {
        s += __shfl_down_sync(0xffffffffu, s, o);
        d += __shfl_down_sync(0xffffffffu, d, o);
    }
    if (lane == 0) { g_as2[node] = s; g_ad2[node] = d; }
}

// ---------- edge softmax layer 1: one warp per dst, 4 heads x 8 lanes ----------
__global__ __launch_bounds__(256)
void escore1_kernel() {
    int w = (blockIdx.x * blockDim.x + threadIdx.x) >> 5;   // dst node
    if (w >= NN) return;
    int lane = threadIdx.x & 31;
    int h = lane >> 3, sl = lane & 7;
    int beg = g_rowptr[w], end = g_rowptr[w + 1];
    float adv = g_ad1[w * 4 + h];

    float m = -1e30f;
    for (int i = beg + sl; i < end; i += 8)
        m = fmaxf(m, lrelu(g_as1[g_csrsrc[i] * 4 + h] + adv));
    #pragma unroll
    for (int o = 4; o > 0; o >>= 1)
        m = fmaxf(m, __shfl_xor_sync(0xffffffffu, m, o, 8));

    float den = 0.f;
    for (int i = beg + sl; i < end; i += 8) {
        float p = __expf(lrelu(g_as1[g_csrsrc[i] * 4 + h] + adv) - m);
        den += p;
        g_p1[(long long)i * 4 + h] = p;
    }
    #pragma unroll
    for (int o = 4; o > 0; o >>= 1)
        den += __shfl_xor_sync(0xffffffffu, den, o, 8);
    if (sl == 0) g_den1[w * 4 + h] = den;
}

// ---------- edge softmax layer 2: one warp per dst ----------
__global__ __launch_bounds__(256)
void escore2_kernel() {
    int w = (blockIdx.x * blockDim.x + threadIdx.x) >> 5;
    if (w >= NN) return;
    int lane = threadIdx.x & 31;
    int beg = g_rowptr[w], end = g_rowptr[w + 1];
    float adv = g_ad2[w];

    float m = -1e30f;
    for (int i = beg + lane; i < end; i += 32)
        m = fmaxf(m, lrelu(g_as2[g_csrsrc[i]] + adv));
    #pragma unroll
    for (int o = 16; o > 0; o >>= 1)
        m = fmaxf(m, __shfl_xor_sync(0xffffffffu, m, o));

    float den = 0.f;
    for (int i = beg + lane; i < end; i += 32) {
        float p = __expf(lrelu(g_as2[g_csrsrc[i]] + adv) - m);
        den += p;
        g_p2[i] = p;
    }
    #pragma unroll
    for (int o = 16; o > 0; o >>= 1)
        den += __shfl_xor_sync(0xffffffffu, den, o);
    if (lane == 0) g_den2[w] = den;
}

// ------- layer 1 aggregation: pure gather+fma, 64 threads per dst -------
__global__ __launch_bounds__(64)
void agg1_kernel(const float* __restrict__ b1) {
    int d = blockIdx.x;
    int t = threadIdx.x;
    int h = t >> 4;
    int beg = g_rowptr[d], end = g_rowptr[d + 1];
    float inv = 1.f / (g_den1[d * 4 + h] + 1e-16f);

    const float4* __restrict__ h1v = (const float4*)g_h1;
    float ax = 0.f, ay = 0.f, az = 0.f, aw = 0.f;
    int i = beg;
    for (; i + 1 < end; i += 2) {
        int s0 = g_csrsrc[i], s1 = g_csrsrc[i + 1];
        float p0 = g_p1[(long long)i * 4 + h];
        float p1 = g_p1[(long long)(i + 1) * 4 + h];
        float4 v0 = h1v[(long long)s0 * 64 + t];
        float4 v1 = h1v[(long long)s1 * 64 + t];
        ax = fmaf(p0, v0.x, ax); ax = fmaf(p1, v1.x, ax);
        ay = fmaf(p0, v0.y, ay); ay = fmaf(p1, v1.y, ay);
        az = fmaf(p0, v0.z, az); az = fmaf(p1, v1.z, az);
        aw = fmaf(p0, v0.w, aw); aw = fmaf(p1, v1.w, aw);
    }
    if (i < end) {
        int s0 = g_csrsrc[i];
        float p0 = g_p1[(long long)i * 4 + h];
        float4 v0 = h1v[(long long)s0 * 64 + t];
        ax = fmaf(p0, v0.x, ax); ay = fmaf(p0, v0.y, ay);
        az = fmaf(p0, v0.z, az); aw = fmaf(p0, v0.w, aw);
    }
    float4 bv = ((const float4*)b1)[t];
    float4 o;
    o.x = fmaxf(ax * inv + bv.x, 0.f);
    o.y = fmaxf(ay * inv + bv.y, 0.f);
    o.z = fmaxf(az * inv + bv.z, 0.f);
    o.w = fmaxf(aw * inv + bv.w, 0.f);
    ((float4*)g_out1)[(long long)d * 64 + t] = o;
}

// ------- layer 2 aggregation: pure gather+fma, 4 dsts per 64-thread block -------
__global__ __launch_bounds__(64)
void agg2_kernel(const float* __restrict__ b2, float* __restrict__ out) {
    int t = threadIdx.x;
    int g = t >> 4;
    int l = t & 15;
    int d = blockIdx.x * 4 + g;
    if (d >= NN) return;
    int beg = g_rowptr[d], end = g_rowptr[d + 1];
    float inv = 1.f / (g_den2[d] + 1e-16f);

    const float4* __restrict__ h2v = (const float4*)g_h2;
    float ax = 0.f, ay = 0.f, az = 0.f, aw = 0.f;
    int i = beg;
    for (; i + 1 < end; i += 2) {
        int s0 = g_csrsrc[i], s1 = g_csrsrc[i + 1];
        float p0 = g_p2[i], p1 = g_p2[i + 1];
        float4 v0 = h2v[(long long)s0 * 16 + l];
        float4 v1 = h2v[(long long)s1 * 16 + l];
        ax = fmaf(p0, v0.x, ax); ax = fmaf(p1, v1.x, ax);
        ay = fmaf(p0, v0.y, ay); ay = fmaf(p1, v1.y, ay);
        az = fmaf(p0, v0.z, az); az = fmaf(p1, v1.z, az);
        aw = fmaf(p0, v0.w, aw); aw = fmaf(p1, v1.w, aw);
    }
    if (i < end) {
        int s0 = g_csrsrc[i];
        float p0 = g_p2[i];
        float4 v0 = h2v[(long long)s0 * 16 + l];
        ax = fmaf(p0, v0.x, ax); ay = fmaf(p0, v0.y, ay);
        az = fmaf(p0, v0.z, az); aw = fmaf(p0, v0.w, aw);
    }
    float4 bv = ((const float4*)b2)[l];
    float4 o;
    o.x = ax * inv + bv.x;
    o.y = ay * inv + bv.y;
    o.z = az * inv + bv.z;
    o.w = aw * inv + bv.w;
    ((float4*)out)[(long long)d * 16 + l] = o;
}

// ---------------- launch ----------------
extern "C" void kernel_launch(void* const* d_in, const int* in_sizes, int n_in,
                              void* d_out, int out_size) {
    const float* x      = (const float*)d_in[0];
    const int*   edge   = (const int*)d_in[1];   // int32 (JAX x64 disabled)
    const float* W1     = (const float*)d_in[2];
    const float* a_src1 = (const float*)d_in[3];
    const float* a_dst1 = (const float*)d_in[4];
    const float* b1     = (const float*)d_in[5];
    const float* W2     = (const float*)d_in[6];
    const float* a_src2 = (const float*)d_in[7];
    const float* a_dst2 = (const float*)d_in[8];
    const float* b2     = (const float*)d_in[9];
    float* out = (float*)d_out;

    k_deg_init<<<(NN + 255) / 256, 256>>>();
    k_count<<<(NE + 255) / 256, 256>>>(edge);
    k_scan<<<1, 1024>>>();

    // idx 3: GEMM1 (profiled slot)
    {
        dim3 grid((NN + 127) / 128, F1 / 128);
        sgemm1_kernel<<<grid, 256>>>(x, W1);
    }

    k_scatter<<<(NT + 255) / 256, 256>>>(edge);
    alpha1_kernel<<<(NN + 1) / 2, 256>>>(a_src1, a_dst1);
    escore1_kernel<<<(NN * 32 + 255) / 256, 256>>>();
    agg1_kernel<<<NN, 64>>>(b1);

    {
        dim3 grid((NN + 127) / 128, 1);
        sgemm2_kernel<<<grid, 256>>>(W2);
    }
    alpha2_kernel<<<(NN + 7) / 8, 256>>>(a_src2, a_dst2);
    escore2_kernel<<<(NN * 32 + 255) / 256, 256>>>();
    agg2_kernel<<<(NN + 3) / 4, 64>>>(b2, out);
}

// round 9
// speedup vs baseline: 1.0121x; 1.0121x over previous
#include <cuda_runtime.h>
#include <cuda_bf16.h>
#include <cuda_fp16.h>
#include <math.h>

#define NN 50000
#define NE 800000
#define NT (NE + NN)
#define FIN 128
#define F1 256
#define H1HEADS 4
#define F2 64
#define NEG_SLOPE 0.2f

// -------- scratch (device globals) --------
__device__ float  g_h1[NN * F1];
__device__ __half g_h1h[NN * F1];    // fp16 mirror for gather
__device__ float  g_out1[NN * F1];
__device__ float  g_h2[NN * F2];
__device__ __half g_h2h[NN * F2];    // fp16 mirror for gather
__device__ float  g_as1[NN * H1HEADS];
__device__ float  g_ad1[NN * H1HEADS];
__device__ float  g_as2[NN];
__device__ float  g_ad2[NN];
__device__ float  g_p1[(long long)NT * 4];
__device__ float  g_den1[NN * 4];
__device__ float  g_p2[NT];
__device__ float  g_den2[NN];
__device__ int    g_deg[NN];
__device__ int    g_rowptr[NN + 1];
__device__ int    g_fill[NN];
__device__ int    g_csrsrc[NT];

// ---------------- packed fp32x2 helpers (sm_100+) ----------------
__device__ __forceinline__ unsigned long long pack2(float x) {
    unsigned long long r;
    asm("mov.b64 %0, {%1, %1};" : "=l"(r) : "f"(x));
    return r;
}
__device__ __forceinline__ void fma2(unsigned long long& d,
                                     unsigned long long a,
                                     unsigned long long b) {
    asm("fma.rn.f32x2 %0, %1, %2, %0;" : "+l"(d) : "l"(a), "l"(b));
}
__device__ __forceinline__ float2 unpack2(unsigned long long v) {
    float2 f;
    asm("mov.b64 {%0, %1}, %2;" : "=f"(f.x), "=f"(f.y) : "l"(v));
    return f;
}

__device__ __forceinline__ float lrelu(float x) {
    return x > 0.f ? x : NEG_SLOPE * x;
}

// ---------------- CSR build ----------------
__global__ void k_deg_init() {
    int i = blockIdx.x * blockDim.x + threadIdx.x;
    if (i < NN) g_deg[i] = 1;   // self loop
}

__global__ void k_count(const int* __restrict__ edge) {
    int e = blockIdx.x * blockDim.x + threadIdx.x;
    if (e < NE) atomicAdd(&g_deg[edge[NE + e]], 1);
}

__global__ __launch_bounds__(1024) void k_scan() {
    __shared__ int sw[33];
    __shared__ int s_base;
    if (threadIdx.x == 0) s_base = 0;
    __syncthreads();
    const int lane = threadIdx.x & 31, warp = threadIdx.x >> 5;
    for (int base = 0; base < NN; base += 4096) {
        int idx = base + threadIdx.x * 4;
        int v0 = 0, v1 = 0, v2 = 0, v3 = 0;
        if (idx + 3 < NN) {
            int4 v = *(const int4*)&g_deg[idx];
            v0 = v.x; v1 = v.y; v2 = v.z; v3 = v.w;
        } else {
            if (idx     < NN) v0 = g_deg[idx];
            if (idx + 1 < NN) v1 = g_deg[idx + 1];
            if (idx + 2 < NN) v2 = g_deg[idx + 2];
            if (idx + 3 < NN) v3 = g_deg[idx + 3];
        }
        int s0 = v0, s1 = s0 + v1, s2 = s1 + v2, s3 = s2 + v3;
        int incl = s3;
        #pragma unroll
        for (int o = 1; o < 32; o <<= 1) {
            int t = __shfl_up_sync(0xffffffffu, incl, o);
            if (lane >= o) incl += t;
        }
        if (lane == 31) sw[warp + 1] = incl;
        __syncthreads();
        if (threadIdx.x == 0) {
            sw[0] = 0;
            int acc = 0;
            #pragma unroll
            for (int w = 1; w <= 32; w++) { acc += sw[w]; sw[w] = acc; }
        }
        __syncthreads();
        int tbase = s_base + sw[warp] + (incl - s3);
        if (idx     < NN) { g_rowptr[idx]     = tbase;      g_fill[idx]     = tbase; }
        if (idx + 1 < NN) { g_rowptr[idx + 1] = tbase + s0; g_fill[idx + 1] = tbase + s0; }
        if (idx + 2 < NN) { g_rowptr[idx + 2] = tbase + s1; g_fill[idx + 2] = tbase + s1; }
        if (idx + 3 < NN) { g_rowptr[idx + 3] = tbase + s2; g_fill[idx + 3] = tbase + s2; }
        __syncthreads();
        if (threadIdx.x == 0) s_base += sw[32];
        __syncthreads();
    }
    if (threadIdx.x == 0) g_rowptr[NN] = s_base;
}

__global__ void k_scatter(const int* __restrict__ edge) {
    int t = blockIdx.x * blockDim.x + threadIdx.x;
    if (t < NE) {
        int d = edge[NE + t];
        int s = edge[t];
        int pos = atomicAdd(&g_fill[d], 1);
        g_csrsrc[pos] = s;
    } else if (t < NT) {
        int i = t - NE;
        int pos = atomicAdd(&g_fill[i], 1);
        g_csrsrc[pos] = i;
    }
}

// --- double-buffered SGEMM, packed f32x2 mainloop; epilogue writes fp32 + fp16 ---
template <int BM, int BN, int BK, int TM, int TN>
__device__ __forceinline__
void sgemm_body(const float* __restrict__ A, const float* __restrict__ B,
                float* __restrict__ C, __half* __restrict__ Ch,
                int M, int K, int N) {
    constexpr int THREADS = 256;
    constexpr int NA = BM * BK / 4 / THREADS;
    constexpr int NB = BK * BN / 4 / THREADS;
    constexpr int TN2 = TN / 2;
    __shared__ float As[2][BK][BM + 4];
    __shared__ float Bs[2][BK][BN];
    const int tx = threadIdx.x;
    const int tcol = tx % (BN / TN);
    const int trow = tx / (BN / TN);
    const int rowBase = blockIdx.x * BM;
    const int colBase = blockIdx.y * BN;

    float4 aReg[NA], bReg[NB];

    unsigned long long acc2[TM][TN2];
    #pragma unroll
    for (int i = 0; i < TM; i++)
        #pragma unroll
        for (int j = 0; j < TN2; j++) acc2[i][j] = 0ull;

    #pragma unroll
    for (int i = 0; i < NA; i++) {
        int id = tx + i * THREADS;
        int r = id / (BK / 4), c4 = id % (BK / 4);
        int gr = rowBase + r;
        aReg[i] = (gr < M) ? *(const float4*)&A[(long long)gr * K + c4 * 4]
                           : make_float4(0.f, 0.f, 0.f, 0.f);
    }
    #pragma unroll
    for (int i = 0; i < NB; i++) {
        int id = tx + i * THREADS;
        int r = id / (BN / 4), c4 = id % (BN / 4);
        bReg[i] = *(const float4*)&B[r * N + colBase + c4 * 4];
    }
    #pragma unroll
    for (int i = 0; i < NA; i++) {
        int id = tx + i * THREADS;
        int r = id / (BK / 4), c4 = id % (BK / 4);
        As[0][c4 * 4 + 0][r] = aReg[i].x;
        As[0][c4 * 4 + 1][r] = aReg[i].y;
        As[0][c4 * 4 + 2][r] = aReg[i].z;
        As[0][c4 * 4 + 3][r] = aReg[i].w;
    }
    #pragma unroll
    for (int i = 0; i < NB; i++) {
        int id = tx + i * THREADS;
        int r = id / (BN / 4), c4 = id % (BN / 4);
        *(float4*)&Bs[0][r][c4 * 4] = bReg[i];
    }
    __syncthreads();

    const int nt = K / BK;
    for (int t = 0; t < nt; t++) {
        const int buf = t & 1;
        if (t + 1 < nt) {
            const int k0 = (t + 1) * BK;
            #pragma unroll
            for (int i = 0; i < NA; i++) {
                int id = tx + i * THREADS;
                int r = id / (BK / 4), c4 = id % (BK / 4);
                int gr = rowBase + r;
                aReg[i] = (gr < M) ? *(const float4*)&A[(long long)gr * K + k0 + c4 * 4]
                                   : make_float4(0.f, 0.f, 0.f, 0.f);
            }
            #pragma unroll
            for (int i = 0; i < NB; i++) {
                int id = tx + i * THREADS;
                int r = id / (BN / 4), c4 = id % (BN / 4);
                bReg[i] = *(const float4*)&B[(k0 + r) * N + colBase + c4 * 4];
            }
        }
        #pragma unroll
        for (int k = 0; k < BK; k++) {
            float a[TM];
            unsigned long long a2[TM], b2[TN2];
            #pragma unroll
            for (int i = 0; i < TM; i += 4)
                *(float4*)&a[i] = *(const float4*)&As[buf][k][trow * TM + i];
            #pragma unroll
            for (int i = 0; i < TM; i++) a2[i] = pack2(a[i]);
            #pragma unroll
            for (int j = 0; j < TN2; j += 2) {
                ulonglong2 bb = *(const ulonglong2*)&Bs[buf][k][tcol * TN + j * 2];
                b2[j] = bb.x; b2[j + 1] = bb.y;
            }
            #pragma unroll
            for (int i = 0; i < TM; i++)
                #pragma unroll
                for (int j = 0; j < TN2; j++)
                    fma2(acc2[i][j], a2[i], b2[j]);
        }
        if (t + 1 < nt) {
            __syncthreads();
            #pragma unroll
            for (int i = 0; i < NA; i++) {
                int id = tx + i * THREADS;
                int r = id / (BK / 4), c4 = id % (BK / 4);
                As[buf ^ 1][c4 * 4 + 0][r] = aReg[i].x;
                As[buf ^ 1][c4 * 4 + 1][r] = aReg[i].y;
                As[buf ^ 1][c4 * 4 + 2][r] = aReg[i].z;
                As[buf ^ 1][c4 * 4 + 3][r] = aReg[i].w;
            }
            #pragma unroll
            for (int i = 0; i < NB; i++) {
                int id = tx + i * THREADS;
                int r = id / (BN / 4), c4 = id % (BN / 4);
                *(float4*)&Bs[buf ^ 1][r][c4 * 4] = bReg[i];
            }
            __syncthreads();
        }
    }
    #pragma unroll
    for (int i = 0; i < TM; i++) {
        int gr = rowBase + trow * TM + i;
        if (gr < M) {
            long long off = (long long)gr * N + colBase + tcol * TN;
            // fp32 store
            #pragma unroll
            for (int j = 0; j < TN2; j += 2) {
                ulonglong2 st;
                st.x = acc2[i][j];
                st.y = acc2[i][j + 1];
                *(ulonglong2*)&C[off + j * 2] = st;
            }
            // fp16 store: TN halfs = TN*2 bytes (16B for TN=8, 8B for TN=4)
            __half2 hh[TN2];
            #pragma unroll
            for (int j = 0; j < TN2; j++) {
                float2 f = unpack2(acc2[i][j]);
                hh[j] = __float22half2_rn(f);
            }
            if (TN2 == 4) {
                *(uint4*)&Ch[off] = *(uint4*)hh;           // 16 bytes (8 halfs)
            } else {
                *(uint2*)&Ch[off] = *(uint2*)hh;           // 8 bytes (4 halfs)
            }
        }
    }
}

__global__ __launch_bounds__(256, 2)
void sgemm1_kernel(const float* __restrict__ A, const float* __restrict__ B) {
    sgemm_body<128, 128, 16, 8, 8>(A, B, g_h1, g_h1h, NN, FIN, F1);
}

__global__ __launch_bounds__(256, 2)
void sgemm2_kernel(const float* __restrict__ B) {
    sgemm_body<128, 64, 16, 8, 4>(g_out1, B, g_h2, g_h2h, NN, F1, F2);
}

// ---------------- alpha projections ----------------
__global__ void alpha1_kernel(const float* __restrict__ a_src,
                              const float* __restrict__ a_dst) {
    int warp = threadIdx.x >> 5, lane = threadIdx.x & 31;
    int node = blockIdx.x * 2 + (warp >> 2);
    int h = warp & 3;
    if (node >= NN) return;
    const float* row = g_h1 + (long long)node * F1 + h * 64;
    float v0 = row[lane], v1 = row[lane + 32];
    float s = v0 * a_src[h * 64 + lane] + v1 * a_src[h * 64 + lane + 32];
    float d = v0 * a_dst[h * 64 + lane] + v1 * a_dst[h * 64 + lane + 32];
    #pragma unroll
    for (int o = 16; o > 0; o >>= 1) {
        s += __shfl_down_sync(0xffffffffu, s, o);
        d += __shfl_down_sync(0xffffffffu, d, o);
    }
    if (lane == 0) { g_as1[node * 4 + h] = s; g_ad1[node * 4 + h] = d; }
}

__global__ void alpha2_kernel(const float* __restrict__ a_src,
                              const float* __restrict__ a_dst) {
    int warp = threadIdx.x >> 5, lane = threadIdx.x & 31;
    int node = blockIdx.x * 8 + warp;
    if (node >= NN) return;
    float v0 = g_h2[(long long)node * F2 + lane];
    float v1 = g_h2[(long long)node * F2 + lane + 32];
    float s = v0 * a_src[lane] + v1 * a_src[lane + 32];
    float d = v0 * a_dst[lane] + v1 * a_dst[lane + 32];
    #pragma unroll
    for (int o = 16; o > 0; o >>= 1) {
        s += __shfl_down_sync(0xffffffffu, s, o);
        d += __shfl_down_sync(0xffffffffu, d, o);
    }
    if (lane == 0) { g_as2[node] = s; g_ad2[node] = d; }
}

// ---------- edge softmax layer 1: one warp per dst, 4 heads x 8 lanes ----------
__global__ __launch_bounds__(256)
void escore1_kernel() {
    int w = (blockIdx.x * blockDim.x + threadIdx.x) >> 5;
    if (w >= NN) return;
    int lane = threadIdx.x & 31;
    int h = lane >> 3, sl = lane & 7;
    int beg = g_rowptr[w], end = g_rowptr[w + 1];
    float adv = g_ad1[w * 4 + h];

    float m = -1e30f;
    for (int i = beg + sl; i < end; i += 8)
        m = fmaxf(m, lrelu(g_as1[g_csrsrc[i] * 4 + h] + adv));
    #pragma unroll
    for (int o = 4; o > 0; o >>= 1)
        m = fmaxf(m, __shfl_xor_sync(0xffffffffu, m, o, 8));

    float den = 0.f;
    for (int i = beg + sl; i < end; i += 8) {
        float p = __expf(lrelu(g_as1[g_csrsrc[i] * 4 + h] + adv) - m);
        den += p;
        g_p1[(long long)i * 4 + h] = p;
    }
    #pragma unroll
    for (int o = 4; o > 0; o >>= 1)
        den += __shfl_xor_sync(0xffffffffu, den, o, 8);
    if (sl == 0) g_den1[w * 4 + h] = den;
}

// ---------- edge softmax layer 2: one warp per dst ----------
__global__ __launch_bounds__(256)
void escore2_kernel() {
    int w = (blockIdx.x * blockDim.x + threadIdx.x) >> 5;
    if (w >= NN) return;
    int lane = threadIdx.x & 31;
    int beg = g_rowptr[w], end = g_rowptr[w + 1];
    float adv = g_ad2[w];

    float m = -1e30f;
    for (int i = beg + lane; i < end; i += 32)
        m = fmaxf(m, lrelu(g_as2[g_csrsrc[i]] + adv));
    #pragma unroll
    for (int o = 16; o > 0; o >>= 1)
        m = fmaxf(m, __shfl_xor_sync(0xffffffffu, m, o));

    float den = 0.f;
    for (int i = beg + lane; i < end; i += 32) {
        float p = __expf(lrelu(g_as2[g_csrsrc[i]] + adv) - m);
        den += p;
        g_p2[i] = p;
    }
    #pragma unroll
    for (int o = 16; o > 0; o >>= 1)
        den += __shfl_xor_sync(0xffffffffu, den, o);
    if (lane == 0) g_den2[w] = den;
}

// ------- layer 1 aggregation: fp16 gather + fp32 accumulate, 64 thr/dst -------
__global__ __launch_bounds__(64)
void agg1_kernel(const float* __restrict__ b1) {
    int d = blockIdx.x;
    int t = threadIdx.x;
    int h = t >> 4;
    int beg = g_rowptr[d], end = g_rowptr[d + 1];
    float inv = 1.f / (g_den1[d * 4 + h] + 1e-16f);

    const uint2* __restrict__ h1v = (const uint2*)g_h1h;   // 4 halfs per uint2
    float ax = 0.f, ay = 0.f, az = 0.f, aw = 0.f;
    int i = beg;
    for (; i + 1 < end; i += 2) {
        int s0 = g_csrsrc[i], s1 = g_csrsrc[i + 1];
        float p0 = g_p1[(long long)i * 4 + h];
        float p1 = g_p1[(long long)(i + 1) * 4 + h];
        uint2 r0 = h1v[(long long)s0 * 64 + t];
        uint2 r1 = h1v[(long long)s1 * 64 + t];
        float2 f0a = __half22float2(*(__half2*)&r0.x);
        float2 f0b = __half22float2(*(__half2*)&r0.y);
        float2 f1a = __half22float2(*(__half2*)&r1.x);
        float2 f1b = __half22float2(*(__half2*)&r1.y);
        ax = fmaf(p0, f0a.x, ax); ax = fmaf(p1, f1a.x, ax);
        ay = fmaf(p0, f0a.y, ay); ay = fmaf(p1, f1a.y, ay);
        az = fmaf(p0, f0b.x, az); az = fmaf(p1, f1b.x, az);
        aw = fmaf(p0, f0b.y, aw); aw = fmaf(p1, f1b.y, aw);
    }
    if (i < end) {
        int s0 = g_csrsrc[i];
        float p0 = g_p1[(long long)i * 4 + h];
        uint2 r0 = h1v[(long long)s0 * 64 + t];
        float2 f0a = __half22float2(*(__half2*)&r0.x);
        float2 f0b = __half22float2(*(__half2*)&r0.y);
        ax = fmaf(p0, f0a.x, ax); ay = fmaf(p0, f0a.y, ay);
        az = fmaf(p0, f0b.x, az); aw = fmaf(p0, f0b.y, aw);
    }
    float4 bv = ((const float4*)b1)[t];
    float4 o;
    o.x = fmaxf(ax * inv + bv.x, 0.f);
    o.y = fmaxf(ay * inv + bv.y, 0.f);
    o.z = fmaxf(az * inv + bv.z, 0.f);
    o.w = fmaxf(aw * inv + bv.w, 0.f);
    ((float4*)g_out1)[(long long)d * 64 + t] = o;
}

// ------- layer 2 aggregation: fp16 gather, 4 dsts per 64-thread block -------
__global__ __launch_bounds__(64)
void agg2_kernel(const float* __restrict__ b2, float* __restrict__ out) {
    int t = threadIdx.x;
    int g = t >> 4;
    int l = t & 15;
    int d = blockIdx.x * 4 + g;
    if (d >= NN) return;
    int beg = g_rowptr[d], end = g_rowptr[d + 1];
    float inv = 1.f / (g_den2[d] + 1e-16f);

    const uint2* __restrict__ h2v = (const uint2*)g_h2h;
    float ax = 0.f, ay = 0.f, az = 0.f, aw = 0.f;
    int i = beg;
    for (; i + 1 < end; i += 2) {
        int s0 = g_csrsrc[i], s1 = g_csrsrc[i + 1];
        float p0 = g_p2[i], p1 = g_p2[i + 1];
        uint2 r0 = h2v[(long long)s0 * 16 + l];
        uint2 r1 = h2v[(long long)s1 * 16 + l];
        float2 f0a = __half22float2(*(__half2*)&r0.x);
        float2 f0b = __half22float2(*(__half2*)&r0.y);
        float2 f1a = __half22float2(*(__half2*)&r1.x);
        float2 f1b = __half22float2(*(__half2*)&r1.y);
        ax = fmaf(p0, f0a.x, ax); ax = fmaf(p1, f1a.x, ax);
        ay = fmaf(p0, f0a.y, ay); ay = fmaf(p1, f1a.y, ay);
        az = fmaf(p0, f0b.x, az); az = fmaf(p1, f1b.x, az);
        aw = fmaf(p0, f0b.y, aw); aw = fmaf(p1, f1b.y, aw);
    }
    if (i < end) {
        int s0 = g_csrsrc[i];
        float p0 = g_p2[i];
        uint2 r0 = h2v[(long long)s0 * 16 + l];
        float2 f0a = __half22float2(*(__half2*)&r0.x);
        float2 f0b = __half22float2(*(__half2*)&r0.y);
        ax = fmaf(p0, f0a.x, ax); ay = fmaf(p0, f0a.y, ay);
        az = fmaf(p0, f0b.x, az); aw = fmaf(p0, f0b.y, aw);
    }
    float4 bv = ((const float4*)b2)[l];
    float4 o;
    o.x = ax * inv + bv.x;
    o.y = ay * inv + bv.y;
    o.z = az * inv + bv.z;
    o.w = aw * inv + bv.w;
    ((float4*)out)[(long long)d * 16 + l] = o;
}

// ---------------- launch ----------------
extern "C" void kernel_launch(void* const* d_in, const int* in_sizes, int n_in,
                              void* d_out, int out_size) {
    const float* x      = (const float*)d_in[0];
    const int*   edge   = (const int*)d_in[1];   // int32 (JAX x64 disabled)
    const float* W1     = (const float*)d_in[2];
    const float* a_src1 = (const float*)d_in[3];
    const float* a_dst1 = (const float*)d_in[4];
    const float* b1     = (const float*)d_in[5];
    const float* W2     = (const float*)d_in[6];
    const float* a_src2 = (const float*)d_in[7];
    const float* a_dst2 = (const float*)d_in[8];
    const float* b2     = (const float*)d_in[9];
    float* out = (float*)d_out;

    k_deg_init<<<(NN + 255) / 256, 256>>>();
    k_count<<<(NE + 255) / 256, 256>>>(edge);
    k_scan<<<1, 1024>>>();

    // idx 3: GEMM1 (profiled slot — expect unchanged ~88us)
    {
        dim3 grid((NN + 127) / 128, F1 / 128);
        sgemm1_kernel<<<grid, 256>>>(x, W1);
    }

    k_scatter<<<(NT + 255) / 256, 256>>>(edge);
    alpha1_kernel<<<(NN + 1) / 2, 256>>>(a_src1, a_dst1);
    escore1_kernel<<<(NN * 32 + 255) / 256, 256>>>();
    agg1_kernel<<<NN, 64>>>(b1);

    {
        dim3 grid((NN + 127) / 128, 1);
        sgemm2_kernel<<<grid, 256>>>(W2);
    }
    alpha2_kernel<<<(NN + 7) / 8, 256>>>(a_src2, a_dst2);
    escore2_kernel<<<(NN * 32 + 255) / 256, 256>>>();
    agg2_kernel<<<(NN + 3) / 4, 64>>>(b2, out);
}

// round 10
// speedup vs baseline: 1.4159x; 1.3990x over previous
#include <cuda_runtime.h>
#include <cuda_bf16.h>
#include <cuda_fp16.h>
#include <mma.h>
#include <math.h>

using namespace nvcuda;

#define NN 50000
#define NNP 50048            // padded to multiple of 128 for WMMA tiles
#define NE 800000
#define NT (NE + NN)
#define FIN 128
#define F1 256
#define H1HEADS 4
#define F2 64
#define NEG_SLOPE 0.2f

// -------- scratch (device globals; zero-initialized at load) --------
__device__ __half g_xh[NNP * FIN];     // fp16 input features
__device__ __half g_w1h[FIN * F1];
__device__ __half g_w2h[F1 * F2];
__device__ float  g_h1[NNP * F1];      // layer1 pre-agg features (fp32, scores)
__device__ __half g_h1h[NNP * F1];     // fp16 mirror for gather (written by alpha1)
__device__ __half g_out1h[NNP * F1];   // relu(gat1) fp16 (GEMM2 input, written by agg1)
__device__ float  g_h2[NNP * F2];
__device__ __half g_h2h[NNP * F2];     // fp16 mirror (written by alpha2)
__device__ float  g_as1[NN * H1HEADS];
__device__ float  g_ad1[NN * H1HEADS];
__device__ float  g_as2[NN];
__device__ float  g_ad2[NN];
__device__ float  g_p1[(long long)NT * 4];
__device__ float  g_den1[NN * 4];
__device__ float  g_p2[NT];
__device__ float  g_den2[NN];
__device__ int    g_deg[NN];
__device__ int    g_rowptr[NN + 1];
__device__ int    g_fill[NN];
__device__ int    g_csrsrc[NT];

__device__ __forceinline__ float lrelu(float x) {
    return x > 0.f ? x : NEG_SLOPE * x;
}

// ---------------- fp32 -> fp16 conversion (n % 4 == 0) ----------------
__global__ void cvt_f2h(const float* __restrict__ src, __half* __restrict__ dst, int n) {
    int i = (blockIdx.x * blockDim.x + threadIdx.x) * 4;
    if (i < n) {
        float4 v = *(const float4*)&src[i];
        __half2 h0 = __floats2half2_rn(v.x, v.y);
        __half2 h1 = __floats2half2_rn(v.z, v.w);
        uint2 u;
        u.x = *(unsigned int*)&h0;
        u.y = *(unsigned int*)&h1;
        *(uint2*)&dst[i] = u;
    }
}

// ---------------- CSR build ----------------
__global__ void k_deg_init() {
    int i = blockIdx.x * blockDim.x + threadIdx.x;
    if (i < NN) g_deg[i] = 1;   // self loop
}

__global__ void k_count(const int* __restrict__ edge) {
    int e = blockIdx.x * blockDim.x + threadIdx.x;
    if (e < NE) atomicAdd(&g_deg[edge[NE + e]], 1);
}

__global__ __launch_bounds__(1024) void k_scan() {
    __shared__ int sw[33];
    __shared__ int s_base;
    if (threadIdx.x == 0) s_base = 0;
    __syncthreads();
    const int lane = threadIdx.x & 31, warp = threadIdx.x >> 5;
    for (int base = 0; base < NN; base += 4096) {
        int idx = base + threadIdx.x * 4;
        int v0 = 0, v1 = 0, v2 = 0, v3 = 0;
        if (idx + 3 < NN) {
            int4 v = *(const int4*)&g_deg[idx];
            v0 = v.x; v1 = v.y; v2 = v.z; v3 = v.w;
        } else {
            if (idx     < NN) v0 = g_deg[idx];
            if (idx + 1 < NN) v1 = g_deg[idx + 1];
            if (idx + 2 < NN) v2 = g_deg[idx + 2];
            if (idx + 3 < NN) v3 = g_deg[idx + 3];
        }
        int s0 = v0, s1 = s0 + v1, s2 = s1 + v2, s3 = s2 + v3;
        int incl = s3;
        #pragma unroll
        for (int o = 1; o < 32; o <<= 1) {
            int t = __shfl_up_sync(0xffffffffu, incl, o);
            if (lane >= o) incl += t;
        }
        if (lane == 31) sw[warp + 1] = incl;
        __syncthreads();
        if (threadIdx.x == 0) {
            sw[0] = 0;
            int acc = 0;
            #pragma unroll
            for (int w = 1; w <= 32; w++) { acc += sw[w]; sw[w] = acc; }
        }
        __syncthreads();
        int tbase = s_base + sw[warp] + (incl - s3);
        if (idx     < NN) { g_rowptr[idx]     = tbase;      g_fill[idx]     = tbase; }
        if (idx + 1 < NN) { g_rowptr[idx + 1] = tbase + s0; g_fill[idx + 1] = tbase + s0; }
        if (idx + 2 < NN) { g_rowptr[idx + 2] = tbase + s1; g_fill[idx + 2] = tbase + s1; }
        if (idx + 3 < NN) { g_rowptr[idx + 3] = tbase + s2; g_fill[idx + 3] = tbase + s2; }
        __syncthreads();
        if (threadIdx.x == 0) s_base += sw[32];
        __syncthreads();
    }
    if (threadIdx.x == 0) g_rowptr[NN] = s_base;
}

__global__ void k_scatter(const int* __restrict__ edge) {
    int t = blockIdx.x * blockDim.x + threadIdx.x;
    if (t < NE) {
        int d = edge[NE + t];
        int s = edge[t];
        int pos = atomicAdd(&g_fill[d], 1);
        g_csrsrc[pos] = s;
    } else if (t < NT) {
        int i = t - NE;
        int pos = atomicAdd(&g_fill[i], 1);
        g_csrsrc[pos] = i;
    }
}

// ---------------- WMMA GEMM1: g_h1[NNP,256] = g_xh[NNP,128] @ g_w1h[128,256] ----
__global__ __launch_bounds__(256)
void hgemm1_kernel() {
    __shared__ __half As[128][136];
    __shared__ __half Bs[128][136];
    const int tx = threadIdx.x;
    const int rowBase = blockIdx.x * 128;
    const int colBase = blockIdx.y * 128;

    // A tile: 128 rows x 128 k (xh padded; rows >= NN are zeros)
    for (int c = tx; c < 128 * 16; c += 256) {
        int r = c >> 4, c8 = (c & 15) << 3;
        *(uint4*)&As[r][c8] = *(const uint4*)&g_xh[(size_t)(rowBase + r) * FIN + c8];
    }
    // B tile: 128 k x 128 n
    for (int c = tx; c < 128 * 16; c += 256) {
        int r = c >> 4, c8 = (c & 15) << 3;
        *(uint4*)&Bs[r][c8] = *(const uint4*)&g_w1h[(size_t)r * F1 + colBase + c8];
    }
    __syncthreads();

    const int warp = tx >> 5;
    const int wm = warp >> 1;   // 0..3 -> 32-row strip
    const int wn = warp & 1;    // 0..1 -> 64-col strip
    wmma::fragment<wmma::accumulator, 16, 16, 16, float> acc[2][4];
    #pragma unroll
    for (int i = 0; i < 2; i++)
        #pragma unroll
        for (int j = 0; j < 4; j++) wmma::fill_fragment(acc[i][j], 0.f);

    #pragma unroll
    for (int k0 = 0; k0 < FIN; k0 += 16) {
        wmma::fragment<wmma::matrix_a, 16, 16, 16, __half, wmma::row_major> af[2];
        wmma::fragment<wmma::matrix_b, 16, 16, 16, __half, wmma::row_major> bf[4];
        #pragma unroll
        for (int i = 0; i < 2; i++)
            wmma::load_matrix_sync(af[i], &As[wm * 32 + i * 16][k0], 136);
        #pragma unroll
        for (int j = 0; j < 4; j++)
            wmma::load_matrix_sync(bf[j], &Bs[k0][wn * 64 + j * 16], 136);
        #pragma unroll
        for (int i = 0; i < 2; i++)
            #pragma unroll
            for (int j = 0; j < 4; j++)
                wmma::mma_sync(acc[i][j], af[i], bf[j], acc[i][j]);
    }
    #pragma unroll
    for (int i = 0; i < 2; i++)
        #pragma unroll
        for (int j = 0; j < 4; j++)
            wmma::store_matrix_sync(
                &g_h1[(size_t)(rowBase + wm * 32 + i * 16) * F1 + colBase + wn * 64 + j * 16],
                acc[i][j], F1, wmma::mem_row_major);
}

// ---------------- WMMA GEMM2: g_h2[NNP,64] = g_out1h[NNP,256] @ g_w2h[256,64] ---
__global__ __launch_bounds__(256)
void hgemm2_kernel() {
    __shared__ __half As[128][136];
    __shared__ __half Bs[128][72];
    const int tx = threadIdx.x;
    const int rowBase = blockIdx.x * 128;

    const int warp = tx >> 5;
    const int wm = warp >> 1;   // 0..3
    const int wn = warp & 1;    // 0..1 -> 32-col strip
    wmma::fragment<wmma::accumulator, 16, 16, 16, float> acc[2][2];
    #pragma unroll
    for (int i = 0; i < 2; i++)
        #pragma unroll
        for (int j = 0; j < 2; j++) wmma::fill_fragment(acc[i][j], 0.f);

    for (int t = 0; t < 2; t++) {
        const int kBase = t * 128;
        for (int c = tx; c < 128 * 16; c += 256) {
            int r = c >> 4, c8 = (c & 15) << 3;
            *(uint4*)&As[r][c8] =
                *(const uint4*)&g_out1h[(size_t)(rowBase + r) * F1 + kBase + c8];
        }
        for (int c = tx; c < 128 * 8; c += 256) {
            int r = c >> 3, c8 = (c & 7) << 3;
            *(uint4*)&Bs[r][c8] = *(const uint4*)&g_w2h[(size_t)(kBase + r) * F2 + c8];
        }
        __syncthreads();
        #pragma unroll
        for (int k0 = 0; k0 < 128; k0 += 16) {
            wmma::fragment<wmma::matrix_a, 16, 16, 16, __half, wmma::row_major> af[2];
            wmma::fragment<wmma::matrix_b, 16, 16, 16, __half, wmma::row_major> bf[2];
            #pragma unroll
            for (int i = 0; i < 2; i++)
                wmma::load_matrix_sync(af[i], &As[wm * 32 + i * 16][k0], 136);
            #pragma unroll
            for (int j = 0; j < 2; j++)
                wmma::load_matrix_sync(bf[j], &Bs[k0][wn * 32 + j * 16], 72);
            #pragma unroll
            for (int i = 0; i < 2; i++)
                #pragma unroll
                for (int j = 0; j < 2; j++)
                    wmma::mma_sync(acc[i][j], af[i], bf[j], acc[i][j]);
        }
        __syncthreads();
    }
    #pragma unroll
    for (int i = 0; i < 2; i++)
        #pragma unroll
        for (int j = 0; j < 2; j++)
            wmma::store_matrix_sync(
                &g_h2[(size_t)(rowBase + wm * 32 + i * 16) * F2 + wn * 32 + j * 16],
                acc[i][j], F2, wmma::mem_row_major);
}

// ---------------- alpha projections (also emit fp16 mirrors) ----------------
__global__ void alpha1_kernel(const float* __restrict__ a_src,
                              const float* __restrict__ a_dst) {
    int warp = threadIdx.x >> 5, lane = threadIdx.x & 31;
    int node = blockIdx.x * 2 + (warp >> 2);
    int h = warp & 3;
    if (node >= NN) return;
    const float* row = g_h1 + (size_t)node * F1 + h * 64;
    float v0 = row[lane], v1 = row[lane + 32];
    g_h1h[(size_t)node * F1 + h * 64 + lane]      = __float2half_rn(v0);
    g_h1h[(size_t)node * F1 + h * 64 + 32 + lane] = __float2half_rn(v1);
    float s = v0 * a_src[h * 64 + lane] + v1 * a_src[h * 64 + lane + 32];
    float d = v0 * a_dst[h * 64 + lane] + v1 * a_dst[h * 64 + lane + 32];
    #pragma unroll
    for (int o = 16; o > 0; o >>= 1) {
        s += __shfl_down_sync(0xffffffffu, s, o);
        d += __shfl_down_sync(0xffffffffu, d, o);
    }
    if (lane == 0) { g_as1[node * 4 + h] = s; g_ad1[node * 4 + h] = d; }
}

__global__ void alpha2_kernel(const float* __restrict__ a_src,
                              const float* __restrict__ a_dst) {
    int warp = threadIdx.x >> 5, lane = threadIdx.x & 31;
    int node = blockIdx.x * 8 + warp;
    if (node >= NN) return;
    float v0 = g_h2[(size_t)node * F2 + lane];
    float v1 = g_h2[(size_t)node * F2 + lane + 32];
    g_h2h[(size_t)node * F2 + lane]      = __float2half_rn(v0);
    g_h2h[(size_t)node * F2 + 32 + lane] = __float2half_rn(v1);
    float s = v0 * a_src[lane] + v1 * a_src[lane + 32];
    float d = v0 * a_dst[lane] + v1 * a_dst[lane + 32];
    #pragma unroll
    for (int o = 16; o > 0; o >>= 1) {
        s += __shfl_down_sync(0xffffffffu, s, o);
        d += __shfl_down_sync(0xffffffffu, d, o);
    }
    if (lane == 0) { g_as2[node] = s; g_ad2[node] = d; }
}

// ---------- edge softmax layer 1: one warp per dst, 4 heads x 8 lanes ----------
__global__ __launch_bounds__(256)
void escore1_kernel() {
    int w = (blockIdx.x * blockDim.x + threadIdx.x) >> 5;
    if (w >= NN) return;
    int lane = threadIdx.x & 31;
    int h = lane >> 3, sl = lane & 7;
    int beg = g_rowptr[w], end = g_rowptr[w + 1];
    float adv = g_ad1[w * 4 + h];

    float m = -1e30f;
    for (int i = beg + sl; i < end; i += 8)
        m = fmaxf(m, lrelu(g_as1[g_csrsrc[i] * 4 + h] + adv));
    #pragma unroll
    for (int o = 4; o > 0; o >>= 1)
        m = fmaxf(m, __shfl_xor_sync(0xffffffffu, m, o, 8));

    float den = 0.f;
    for (int i = beg + sl; i < end; i += 8) {
        float p = __expf(lrelu(g_as1[g_csrsrc[i] * 4 + h] + adv) - m);
        den += p;
        g_p1[(long long)i * 4 + h] = p;
    }
    #pragma unroll
    for (int o = 4; o > 0; o >>= 1)
        den += __shfl_xor_sync(0xffffffffu, den, o, 8);
    if (sl == 0) g_den1[w * 4 + h] = den;
}

// ---------- edge softmax layer 2: one warp per dst ----------
__global__ __launch_bounds__(256)
void escore2_kernel() {
    int w = (blockIdx.x * blockDim.x + threadIdx.x) >> 5;
    if (w >= NN) return;
    int lane = threadIdx.x & 31;
    int beg = g_rowptr[w], end = g_rowptr[w + 1];
    float adv = g_ad2[w];

    float m = -1e30f;
    for (int i = beg + lane; i < end; i += 32)
        m = fmaxf(m, lrelu(g_as2[g_csrsrc[i]] + adv));
    #pragma unroll
    for (int o = 16; o > 0; o >>= 1)
        m = fmaxf(m, __shfl_xor_sync(0xffffffffu, m, o));

    float den = 0.f;
    for (int i = beg + lane; i < end; i += 32) {
        float p = __expf(lrelu(g_as2[g_csrsrc[i]] + adv) - m);
        den += p;
        g_p2[i] = p;
    }
    #pragma unroll
    for (int o = 16; o > 0; o >>= 1)
        den += __shfl_xor_sync(0xffffffffu, den, o);
    if (lane == 0) g_den2[w] = den;
}

// ------- layer 1 aggregation: fp16 gather + fp32 accumulate, 64 thr/dst -------
// writes relu(out) directly as fp16 (GEMM2 input)
__global__ __launch_bounds__(64)
void agg1_kernel(const float* __restrict__ b1) {
    int d = blockIdx.x;
    int t = threadIdx.x;
    int h = t >> 4;
    int beg = g_rowptr[d], end = g_rowptr[d + 1];
    float inv = 1.f / (g_den1[d * 4 + h] + 1e-16f);

    const uint2* __restrict__ h1v = (const uint2*)g_h1h;
    float ax = 0.f, ay = 0.f, az = 0.f, aw = 0.f;
    int i = beg;
    for (; i + 1 < end; i += 2) {
        int s0 = g_csrsrc[i], s1 = g_csrsrc[i + 1];
        float p0 = g_p1[(long long)i * 4 + h];
        float p1 = g_p1[(long long)(i + 1) * 4 + h];
        uint2 r0 = h1v[(size_t)s0 * 64 + t];
        uint2 r1 = h1v[(size_t)s1 * 64 + t];
        float2 f0a = __half22float2(*(__half2*)&r0.x);
        float2 f0b = __half22float2(*(__half2*)&r0.y);
        float2 f1a = __half22float2(*(__half2*)&r1.x);
        float2 f1b = __half22float2(*(__half2*)&r1.y);
        ax = fmaf(p0, f0a.x, ax); ax = fmaf(p1, f1a.x, ax);
        ay = fmaf(p0, f0a.y, ay); ay = fmaf(p1, f1a.y, ay);
        az = fmaf(p0, f0b.x, az); az = fmaf(p1, f1b.x, az);
        aw = fmaf(p0, f0b.y, aw); aw = fmaf(p1, f1b.y, aw);
    }
    if (i < end) {
        int s0 = g_csrsrc[i];
        float p0 = g_p1[(long long)i * 4 + h];
        uint2 r0 = h1v[(size_t)s0 * 64 + t];
        float2 f0a = __half22float2(*(__half2*)&r0.x);
        float2 f0b = __half22float2(*(__half2*)&r0.y);
        ax = fmaf(p0, f0a.x, ax); ay = fmaf(p0, f0a.y, ay);
        az = fmaf(p0, f0b.x, az); aw = fmaf(p0, f0b.y, aw);
    }
    float4 bv = ((const float4*)b1)[t];
    float ox = fmaxf(ax * inv + bv.x, 0.f);
    float oy = fmaxf(ay * inv + bv.y, 0.f);
    float oz = fmaxf(az * inv + bv.z, 0.f);
    float ow = fmaxf(aw * inv + bv.w, 0.f);
    __half2 ha = __floats2half2_rn(ox, oy);
    __half2 hb = __floats2half2_rn(oz, ow);
    uint2 u;
    u.x = *(unsigned int*)&ha;
    u.y = *(unsigned int*)&hb;
    ((uint2*)g_out1h)[(size_t)d * 64 + t] = u;
}

// ------- layer 2 aggregation: fp16 gather, 4 dsts per 64-thread block -------
__global__ __launch_bounds__(64)
void agg2_kernel(const float* __restrict__ b2, float* __restrict__ out) {
    int t = threadIdx.x;
    int g = t >> 4;
    int l = t & 15;
    int d = blockIdx.x * 4 + g;
    if (d >= NN) return;
    int beg = g_rowptr[d], end = g_rowptr[d + 1];
    float inv = 1.f / (g_den2[d] + 1e-16f);

    const uint2* __restrict__ h2v = (const uint2*)g_h2h;
    float ax = 0.f, ay = 0.f, az = 0.f, aw = 0.f;
    int i = beg;
    for (; i + 1 < end; i += 2) {
        int s0 = g_csrsrc[i], s1 = g_csrsrc[i + 1];
        float p0 = g_p2[i], p1 = g_p2[i + 1];
        uint2 r0 = h2v[(size_t)s0 * 16 + l];
        uint2 r1 = h2v[(size_t)s1 * 16 + l];
        float2 f0a = __half22float2(*(__half2*)&r0.x);
        float2 f0b = __half22float2(*(__half2*)&r0.y);
        float2 f1a = __half22float2(*(__half2*)&r1.x);
        float2 f1b = __half22float2(*(__half2*)&r1.y);
        ax = fmaf(p0, f0a.x, ax); ax = fmaf(p1, f1a.x, ax);
        ay = fmaf(p0, f0a.y, ay); ay = fmaf(p1, f1a.y, ay);
        az = fmaf(p0, f0b.x, az); az = fmaf(p1, f1b.x, az);
        aw = fmaf(p0, f0b.y, aw); aw = fmaf(p1, f1b.y, aw);
    }
    if (i < end) {
        int s0 = g_csrsrc[i];
        float p0 = g_p2[i];
        uint2 r0 = h2v[(size_t)s0 * 16 + l];
        float2 f0a = __half22float2(*(__half2*)&r0.x);
        float2 f0b = __half22float2(*(__half2*)&r0.y);
        ax = fmaf(p0, f0a.x, ax); ay = fmaf(p0, f0a.y, ay);
        az = fmaf(p0, f0b.x, az); aw = fmaf(p0, f0b.y, aw);
    }
    float4 bv = ((const float4*)b2)[l];
    float4 o;
    o.x = ax * inv + bv.x;
    o.y = ay * inv + bv.y;
    o.z = az * inv + bv.z;
    o.w = aw * inv + bv.w;
    ((float4*)out)[(size_t)d * 16 + l] = o;
}

// ---------------- launch ----------------
extern "C" void kernel_launch(void* const* d_in, const int* in_sizes, int n_in,
                              void* d_out, int out_size) {
    const float* x      = (const float*)d_in[0];
    const int*   edge   = (const int*)d_in[1];   // int32 (JAX x64 disabled)
    const float* W1     = (const float*)d_in[2];
    const float* a_src1 = (const float*)d_in[3];
    const float* a_dst1 = (const float*)d_in[4];
    const float* b1     = (const float*)d_in[5];
    const float* W2     = (const float*)d_in[6];
    const float* a_src2 = (const float*)d_in[7];
    const float* a_dst2 = (const float*)d_in[8];
    const float* b2     = (const float*)d_in[9];
    float* out = (float*)d_out;

    __half *xh, *w1h, *w2h;
    // device-symbol addresses resolved on device side; use kernels with symbols
    // conversions (idx 0..2)
    {
        // we can't take symbol addresses on host; use small wrapper kernels via
        // pointer-free dispatch: cvt kernels read from params, write via symbol
    }
    // cvt_x -> g_xh
    extern __global__ void cvt_x_kernel(const float*);
    extern __global__ void cvt_w1_kernel(const float*);
    extern __global__ void cvt_w2_kernel(const float*);
    cvt_x_kernel<<<(NN * FIN / 4 + 255) / 256, 256>>>(x);
    cvt_w1_kernel<<<(FIN * F1 / 4 + 255) / 256, 256>>>(W1);
    cvt_w2_kernel<<<(F1 * F2 / 4 + 255) / 256, 256>>>(W2);

    // idx 3: GEMM1 on tensor cores (profiled slot)
    {
        dim3 grid((NNP) / 128, F1 / 128);
        hgemm1_kernel<<<grid, 256>>>();
    }

    k_deg_init<<<(NN + 255) / 256, 256>>>();
    k_count<<<(NE + 255) / 256, 256>>>(edge);
    k_scan<<<1, 1024>>>();
    k_scatter<<<(NT + 255) / 256, 256>>>(edge);

    alpha1_kernel<<<(NN + 1) / 2, 256>>>(a_src1, a_dst1);
    escore1_kernel<<<(NN * 32 + 255) / 256, 256>>>();
    agg1_kernel<<<NN, 64>>>(b1);

    hgemm2_kernel<<<NNP / 128, 256>>>();
    alpha2_kernel<<<(NN + 7) / 8, 256>>>(a_src2, a_dst2);
    escore2_kernel<<<(NN * 32 + 255) / 256, 256>>>();
    agg2_kernel<<<(NN + 3) / 4, 64>>>(b2, out);
}

// ---- symbol-targeted conversion kernels (defined after use declaration) ----
__global__ void cvt_x_kernel(const float* __restrict__ src) {
    int i = (blockIdx.x * blockDim.x + threadIdx.x) * 4;
    if (i < NN * FIN) {
        float4 v = *(const float4*)&src[i];
        __half2 h0 = __floats2half2_rn(v.x, v.y);
        __half2 h1 = __floats2half2_rn(v.z, v.w);
        uint2 u;
        u.x = *(unsigned int*)&h0;
        u.y = *(unsigned int*)&h1;
        *(uint2*)&g_xh[i] = u;
    }
}
__global__ void cvt_w1_kernel(const float* __restrict__ src) {
    int i = (blockIdx.x * blockDim.x + threadIdx.x) * 4;
    if (i < FIN * F1) {
        float4 v = *(const float4*)&src[i];
        __half2 h0 = __floats2half2_rn(v.x, v.y);
        __half2 h1 = __floats2half2_rn(v.z, v.w);
        uint2 u;
        u.x = *(unsigned int*)&h0;
        u.y = *(unsigned int*)&h1;
        *(uint2*)&g_w1h[i] = u;
    }
}
__global__ void cvt_w2_kernel(const float* __restrict__ src) {
    int i = (blockIdx.x * blockDim.x + threadIdx.x) * 4;
    if (i < F1 * F2) {
        float4 v = *(const float4*)&src[i];
        __half2 h0 = __floats2half2_rn(v.x, v.y);
        __half2 h1 = __floats2half2_rn(v.z, v.w);
        uint2 u;
        u.x = *(unsigned int*)&h0;
        u.y = *(unsigned int*)&h1;
        *(uint2*)&g_w2h[i] = u;
    }
}